// round 12
// baseline (speedup 1.0000x reference)
#include <cuda_runtime.h>
#include <math.h>
#include <cstdint>

// YOLOv1 loss: S=14, B=2, C=20, N=30, BATCH=4096
#define NCELLS        802816
#define CELLS_PER_BLK 128
#define NBLOCKS       (NCELLS / CELLS_PER_BLK)   // 6272
#define THREADS       256                         // 2 warp-groups: box / cls
#define FPC           30
#define INV_S         (1.0f / 14.0f)
#define NV4           (CELLS_PER_BLK * FPC / 4)  // 960 float4 per tile
#define TILE_BYTES    (NV4 * 16)                 // 15360

__device__ double   g_acc   = 0.0;
__device__ unsigned g_count = 0;

__device__ __forceinline__ uint32_t smem_u32(const void* p) {
    return (uint32_t)__cvta_generic_to_shared(p);
}
__device__ __forceinline__ void mbar_init(uint32_t mbar, uint32_t count) {
    asm volatile("mbarrier.init.shared.b64 [%0], %1;" :: "r"(mbar), "r"(count) : "memory");
}
__device__ __forceinline__ void mbar_expect_tx(uint32_t mbar, uint32_t bytes) {
    asm volatile("mbarrier.arrive.expect_tx.shared.b64 _, [%0], %1;"
                 :: "r"(mbar), "r"(bytes) : "memory");
}
__device__ __forceinline__ void bulk_g2s(uint32_t dst, const void* src,
                                         uint32_t bytes, uint32_t mbar) {
    asm volatile("cp.async.bulk.shared::cta.global.mbarrier::complete_tx::bytes "
                 "[%0], [%1], %2, [%3];"
                 :: "r"(dst), "l"(src), "r"(bytes), "r"(mbar) : "memory");
}
__device__ __forceinline__ void mbar_wait(uint32_t mbar, uint32_t parity) {
    uint32_t done;
    asm volatile(
        "{\n\t.reg .pred p;\n\t"
        "mbarrier.try_wait.parity.acquire.cta.shared::cta.b64 p, [%1], %2;\n\t"
        "selp.b32 %0, 1, 0, p;\n\t}"
        : "=r"(done) : "r"(mbar), "r"(parity) : "memory");
    if (!done) {
        asm volatile(
            "{\n\t.reg .pred P1;\n\t"
            "W_%=:\n\t"
            "mbarrier.try_wait.parity.acquire.cta.shared::cta.b64 P1, [%0], %1, 0x989680;\n\t"
            "@P1 bra.uni D_%=;\n\t"
            "bra.uni W_%=;\n\t"
            "D_%=:\n\t}"
            :: "r"(mbar), "r"(parity) : "memory");
    }
}

__global__ __launch_bounds__(THREADS) void yolo_fused(
    const float* __restrict__ pred, const float* __restrict__ targ,
    float* __restrict__ out)
{
    __shared__ alignas(16) float4 s_t[NV4];             // target tile, 15360 B
    __shared__ alignas(16) float4 s_p[NV4];             // pred tile,   15360 B
    __shared__ alignas(8)  unsigned long long mbar_s[2];
    __shared__ float wsum[THREADS / 32];

    const int tid  = threadIdx.x;
    const long long fbase = (long long)blockIdx.x * (CELLS_PER_BLK * FPC);

    const uint32_t mb_t = smem_u32(&mbar_s[0]);
    const uint32_t mb_p = smem_u32(&mbar_s[1]);

    // init + issue from tid0 BEFORE the sync: DRAM streams start immediately.
    if (tid == 0) {
        mbar_init(mb_t, 1);
        mbar_init(mb_p, 1);
        mbar_expect_tx(mb_t, TILE_BYTES);
        bulk_g2s(smem_u32(s_t), targ + fbase, TILE_BYTES, mb_t);
        mbar_expect_tx(mb_p, TILE_BYTES);
        bulk_g2s(smem_u32(s_p), pred + fbase, TILE_BYTES, mb_p);
    }
    __syncthreads();   // others must not wait on uninitialized barriers

    const int  cell   = tid & (CELLS_PER_BLK - 1);   // 0..127
    const bool is_cls = tid >= CELLS_PER_BLK;        // warps 4-7: cls path

    const float2* __restrict__ tp =
        reinterpret_cast<const float2*>(reinterpret_cast<const float*>(s_t) + cell * FPC);
    const float2* __restrict__ pp =
        reinterpret_cast<const float2*>(reinterpret_cast<const float*>(s_p) + cell * FPC);

    float partial;

    if (!is_cls) {
        // =============== BOX path (warps 0-3) ===============
        mbar_wait(mb_t, 0);
        const float2 tA = tp[0];            // t0 t1
        const float2 tB = tp[1];            // t2 t3
        const float  t4 = tp[2].x;
        const bool obj = t4 > 0.0f;

        float tcx = tA.x * INV_S, tcy = tA.y * INV_S;
        float thw = 0.5f * tB.x,  thh = 0.5f * tB.y;
        const float tx0 = tcx - thw, ty0 = tcy - thh;
        const float tx1 = tcx + thw, ty1 = tcy + thh;
        const float area_t = (tx1 - tx0) * (ty1 - ty0);
        const float sqt2 = sqrtf(tB.x), sqt3 = sqrtf(tB.y);

        mbar_wait(mb_p, 0);
        const float2 pA = pp[0];            // p0 p1
        const float2 pB = pp[1];            // p2 p3
        const float2 pC = pp[2];            // p4 p5
        const float2 pD = pp[3];            // p6 p7
        const float2 pE = pp[4];            // p8 p9

        // box0 = (pA.x,pA.y,pB.x,pB.y,pC.x)  box1 = (pC.y,pD.x,pD.y,pE.x,pE.y)
        float iou0, iou1;
        {
            float pcx = pA.x * INV_S, pcy = pA.y * INV_S;
            float phw = 0.5f * pB.x,  phh = 0.5f * pB.y;
            float px0 = pcx - phw, py0 = pcy - phh;
            float px1 = pcx + phw, py1 = pcy + phh;
            float wi = fmaxf(fminf(px1, tx1) - fmaxf(px0, tx0), 0.0f);
            float hi = fmaxf(fminf(py1, ty1) - fmaxf(py0, ty0), 0.0f);
            float inter  = wi * hi;
            float area_p = (px1 - px0) * (py1 - py0);
            iou0 = inter / (area_p + area_t - inter);
        }
        {
            float pcx = pC.y * INV_S, pcy = pD.x * INV_S;
            float phw = 0.5f * pD.y,  phh = 0.5f * pE.x;
            float px0 = pcx - phw, py0 = pcy - phh;
            float px1 = pcx + phw, py1 = pcy + phh;
            float wi = fmaxf(fminf(px1, tx1) - fmaxf(px0, tx0), 0.0f);
            float hi = fmaxf(fminf(py1, ty1) - fmaxf(py0, ty0), 0.0f);
            float inter  = wi * hi;
            float area_p = (px1 - px0) * (py1 - py0);
            iou1 = inter / (area_p + area_t - inter);
        }

        if (obj) {
            // argmax tie-break -> index 0 (matches jnp.argmax)
            const bool  r1   = (iou1 > iou0);
            const float miou = fmaxf(iou0, iou1);
            const float rpx  = r1 ? pC.y : pA.x;
            const float rpy  = r1 ? pD.x : pA.y;
            const float rpw  = r1 ? pD.y : pB.x;
            const float rph  = r1 ? pE.x : pB.y;
            const float rpc  = r1 ? pE.y : pC.x;

            float dx = rpx - tA.x;
            float dy = rpy - tA.y;
            float dxy = dx * dx + dy * dy;

            float dw = sqrtf(rpw) - sqt2;
            float dh = sqrtf(rph) - sqt3;
            float dwh = dw * dw + dh * dh;

            float dob = rpc - miou;
            partial = 5.0f * (dxy + dwh) + dob * dob;
        } else {
            // t4 == 0 exactly -> conf targets are 0 for both boxes
            float d0 = pC.x;
            float d1 = pE.y;
            partial = 0.5f * (d0 * d0 + d1 * d1);
        }
    } else {
        // =============== CLS path (warps 4-7) ===============
        mbar_wait(mb_t, 0);
        const float t4 = tp[2].x;
        float2 tcls[10];
        #pragma unroll
        for (int c = 0; c < 10; ++c) tcls[c] = tp[5 + c];

        mbar_wait(mb_p, 0);
        float q0 = 0.f, q1 = 0.f, q2 = 0.f, q3 = 0.f;
        #pragma unroll
        for (int c = 0; c < 10; c += 2) {
            float2 pc0 = pp[5 + c],     tc0 = tcls[c];
            float2 pc1 = pp[5 + c + 1], tc1 = tcls[c + 1];
            float d0 = pc0.x - tc0.x, d1 = pc0.y - tc0.y;
            float d2 = pc1.x - tc1.x, d3 = pc1.y - tc1.y;
            q0 = fmaf(d0, d0, q0); q1 = fmaf(d1, d1, q1);
            q2 = fmaf(d2, d2, q2); q3 = fmaf(d3, d3, q3);
        }
        // target cls is all-zero when t4==0, but reference gates by obj anyway
        partial = (t4 > 0.0f) ? ((q0 + q1) + (q2 + q3)) : 0.0f;
    }

    // ============ deterministic block reduce (fp32) ============
    #pragma unroll
    for (int o = 16; o > 0; o >>= 1)
        partial += __shfl_down_sync(0xFFFFFFFFu, partial, o);

    const int warp = tid >> 5, lane = tid & 31;
    if (lane == 0) wsum[warp] = partial;
    __syncthreads();

    // ============ fence-free global accumulation ============
    if (tid == 0) {
        float v = ((wsum[0] + wsum[1]) + (wsum[2] + wsum[3]))
                + ((wsum[4] + wsum[5]) + (wsum[6] + wsum[7]));

        double oldacc = atomicAdd(&g_acc, (double)v);

        unsigned dep = 0u;
        unsigned lo  = (unsigned)__double2loint(oldacc);
        asm volatile("" : "+r"(dep) : "r"(lo));   // inc ordered after add

        unsigned oldc = atomicInc(&g_count, (NBLOCKS - 1u) + dep); // wraps to 0
        if (oldc == NBLOCKS - 1u) {
            unsigned long long bits =
                atomicExch(reinterpret_cast<unsigned long long*>(&g_acc), 0ULL);
            out[0] = (float)(__longlong_as_double(bits) * (1.0 / 4096.0));
        }
    }
}

extern "C" void kernel_launch(void* const* d_in, const int* in_sizes, int n_in,
                              void* d_out, int out_size)
{
    const float* pred = (const float*)d_in[0];
    const float* targ = (const float*)d_in[1];
    yolo_fused<<<NBLOCKS, THREADS>>>(pred, targ, (float*)d_out);
}